// round 5
// baseline (speedup 1.0000x reference)
#include <cuda_runtime.h>
#include <math.h>
#include <stdint.h>

// ---------------- problem constants ----------------
#define BB 4
#define NN 1024
#define CC 768
#define HH 12
#define TWO_D 128
#define MROWS (BB*NN)    // 4096
#define SCALE 0.125f     // D^-0.5
#define EPS 1e-5f
#define OUT_SCALE 0.8f   // 1 - LAMBDA_INIT

// ---------------- scratch (device globals; no alloc allowed) ----------------
__device__ float g_xn  [MROWS*CC];
__device__ float g_q   [MROWS*2*CC];
__device__ float g_k   [MROWS*2*CC];
__device__ float g_v   [MROWS*2*CC];
__device__ float g_o1  [MROWS*2*CC];
__device__ float g_o2  [MROWS*2*CC];
__device__ float g_att [MROWS*2*CC];
__device__ float g_xmid[MROWS*CC];
__device__ float g_xn2 [MROWS*CC];
__device__ float g_h   [MROWS*4*CC];

// ================= helpers =================
__device__ __forceinline__ uint32_t f2tf32(float f) {
    uint32_t r;
    asm("cvt.rna.tf32.f32 %0, %1;" : "=r"(r) : "f"(f));
    return r;
}
__device__ __forceinline__ void mma_tf32(float* c, const uint32_t* a, const uint32_t* b) {
    asm volatile("mma.sync.aligned.m16n8k8.row.col.f32.tf32.tf32.f32 "
        "{%0,%1,%2,%3}, {%4,%5,%6,%7}, {%8,%9}, {%0,%1,%2,%3};"
        : "+f"(c[0]), "+f"(c[1]), "+f"(c[2]), "+f"(c[3])
        : "r"(a[0]), "r"(a[1]), "r"(a[2]), "r"(a[3]), "r"(b[0]), "r"(b[1]));
}

// ================= LayerNorm over 768 =================
__global__ __launch_bounds__(256) void ln_kernel(
    const float* __restrict__ x, const float* __restrict__ w,
    const float* __restrict__ b, float* __restrict__ out)
{
    int row = blockIdx.x;
    int tid = threadIdx.x;
    const float* xr = x + (size_t)row * CC;
    float v0 = xr[tid], v1 = xr[tid + 256], v2 = xr[tid + 512];
    float s  = v0 + v1 + v2;
    float sq = v0*v0 + v1*v1 + v2*v2;
#pragma unroll
    for (int off = 16; off >= 1; off >>= 1) {
        s  += __shfl_xor_sync(0xffffffffu, s,  off);
        sq += __shfl_xor_sync(0xffffffffu, sq, off);
    }
    __shared__ float rs_[8], rq_[8];
    __shared__ float smu, srs;
    int wid = tid >> 5, lane = tid & 31;
    if (lane == 0) { rs_[wid] = s; rq_[wid] = sq; }
    __syncthreads();
    if (tid == 0) {
        float S = 0.f, Q = 0.f;
#pragma unroll
        for (int i = 0; i < 8; i++) { S += rs_[i]; Q += rq_[i]; }
        float mu = S / (float)CC;
        float var = Q / (float)CC - mu * mu;
        smu = mu; srs = rsqrtf(var + EPS);
    }
    __syncthreads();
    float mu = smu, r = srs;
    float* orow = out + (size_t)row * CC;
    orow[tid]       = (v0 - mu) * r * w[tid]       + b[tid];
    orow[tid + 256] = (v1 - mu) * r * w[tid + 256] + b[tid + 256];
    orow[tid + 512] = (v2 - mu) * r * w[tid + 512] + b[tid + 512];
}

// ================= TF32 mma.sync GEMM: C = A(MxK) * B(NxK)^T =================
#define KC 32
#define SSTRIDE 36
#define STAGE_U32 (128 * SSTRIDE)

template<int EPI>
__global__ __launch_bounds__(256, 1) void tc_gemm(
    const float* __restrict__ A, const float* __restrict__ B,
    const float* __restrict__ bias, const float* __restrict__ res,
    float* __restrict__ C, int M, int N, int K)
{
    __shared__ uint32_t sA[2][STAGE_U32];
    __shared__ uint32_t sB[2][STAGE_U32];

    int tid  = threadIdx.x;
    int wid  = tid >> 5;
    int lane = tid & 31;
    int wm = wid >> 2;
    int wn = wid & 3;
    int gid = lane >> 2;
    int tig = lane & 3;

    int m0 = blockIdx.y * 128, n0 = blockIdx.x * 128;

    int trow = tid >> 3;
    int tseg = tid & 7;

    float acc[4][4][4];
#pragma unroll
    for (int i = 0; i < 4; i++)
#pragma unroll
        for (int j = 0; j < 4; j++)
#pragma unroll
            for (int r = 0; r < 4; r++) acc[i][j][r] = 0.f;

    float4 av[4], bv[4];
#pragma unroll
    for (int p = 0; p < 4; p++) {
        int r = trow + p * 32;
        av[p] = *(const float4*)(A + (size_t)(m0 + r) * K + tseg * 4);
        bv[p] = *(const float4*)(B + (size_t)(n0 + r) * K + tseg * 4);
    }
#pragma unroll
    for (int p = 0; p < 4; p++) {
        int r = trow + p * 32;
        uint32_t* da = &sA[0][r * SSTRIDE + tseg * 4];
        uint32_t* db = &sB[0][r * SSTRIDE + tseg * 4];
        da[0] = f2tf32(av[p].x); da[1] = f2tf32(av[p].y);
        da[2] = f2tf32(av[p].z); da[3] = f2tf32(av[p].w);
        db[0] = f2tf32(bv[p].x); db[1] = f2tf32(bv[p].y);
        db[2] = f2tf32(bv[p].z); db[3] = f2tf32(bv[p].w);
    }
    __syncthreads();

    int Cn = K / KC;
    for (int c = 0; c < Cn; c++) {
        int s = c & 1;
        if (c + 1 < Cn) {
            int k0 = (c + 1) * KC;
#pragma unroll
            for (int p = 0; p < 4; p++) {
                int r = trow + p * 32;
                av[p] = *(const float4*)(A + (size_t)(m0 + r) * K + k0 + tseg * 4);
                bv[p] = *(const float4*)(B + (size_t)(n0 + r) * K + k0 + tseg * 4);
            }
        }

        const uint32_t* As = sA[s];
        const uint32_t* Bs = sB[s];
#pragma unroll
        for (int ks = 0; ks < 4; ks++) {
            int k0 = ks * 8;
            uint32_t afr[4][4], bfr[4][2];
#pragma unroll
            for (int i = 0; i < 4; i++) {
                int rb = wm * 64 + i * 16;
                afr[i][0] = As[(rb + gid    ) * SSTRIDE + k0 + tig];
                afr[i][1] = As[(rb + 8 + gid) * SSTRIDE + k0 + tig];
                afr[i][2] = As[(rb + gid    ) * SSTRIDE + k0 + 4 + tig];
                afr[i][3] = As[(rb + 8 + gid) * SSTRIDE + k0 + 4 + tig];
            }
#pragma unroll
            for (int j = 0; j < 4; j++) {
                int cb = wn * 32 + j * 8;
                bfr[j][0] = Bs[(cb + gid) * SSTRIDE + k0 + tig];
                bfr[j][1] = Bs[(cb + gid) * SSTRIDE + k0 + 4 + tig];
            }
#pragma unroll
            for (int i = 0; i < 4; i++)
#pragma unroll
                for (int j = 0; j < 4; j++)
                    mma_tf32(acc[i][j], afr[i], bfr[j]);
        }

        if (c + 1 < Cn) {
            int s1 = s ^ 1;
#pragma unroll
            for (int p = 0; p < 4; p++) {
                int r = trow + p * 32;
                uint32_t* da = &sA[s1][r * SSTRIDE + tseg * 4];
                uint32_t* db = &sB[s1][r * SSTRIDE + tseg * 4];
                da[0] = f2tf32(av[p].x); da[1] = f2tf32(av[p].y);
                da[2] = f2tf32(av[p].z); da[3] = f2tf32(av[p].w);
                db[0] = f2tf32(bv[p].x); db[1] = f2tf32(bv[p].y);
                db[2] = f2tf32(bv[p].z); db[3] = f2tf32(bv[p].w);
            }
            __syncthreads();
        }
    }

#pragma unroll
    for (int i = 0; i < 4; i++) {
#pragma unroll
        for (int j = 0; j < 4; j++) {
            int col = n0 + wn * 32 + j * 8 + tig * 2;
#pragma unroll
            for (int half = 0; half < 2; half++) {
                int row = m0 + wm * 64 + i * 16 + gid + half * 8;
                float vx = acc[i][j][half * 2 + 0];
                float vy = acc[i][j][half * 2 + 1];
                if (EPI == 1) {
                    const float* rrow = res + (size_t)row * N + col;
                    vx += bias[col]     + rrow[0];
                    vy += bias[col + 1] + rrow[1];
                } else if (EPI == 2) {
                    vx += bias[col];
                    vy += bias[col + 1];
                    vx = 0.5f * vx * (1.0f + erff(vx * 0.70710678118654752f));
                    vy = 0.5f * vy * (1.0f + erff(vy * 0.70710678118654752f));
                }
                float2 o = make_float2(vx, vy);
                *(float2*)(C + (size_t)row * N + col) = o;
            }
        }
    }
}

// ================= Flash attention (one split per block) on tf32 mma =================
// grid (8, 12, 8): x=q-tile(128 rows), y=head, z=b*2+split. 8 warps x 16 rows.
#define SQ_STR 68
#define SK_STR 68
#define SV_STR 136
#define SQ_SIZE (128*SQ_STR)
#define SK_SIZE (64*SK_STR)
#define SV_SIZE (64*SV_STR)
#define ATT_SMEM ((SQ_SIZE+SK_SIZE+SV_SIZE)*4)

__global__ __launch_bounds__(256, 1) void attn_mma_kernel(
    const float* __restrict__ Q, const float* __restrict__ K,
    const float* __restrict__ Vv, float* __restrict__ O1, float* __restrict__ O2)
{
    extern __shared__ uint32_t asm_[];
    uint32_t* sQ = asm_;
    uint32_t* sK = asm_ + SQ_SIZE;
    uint32_t* sV = asm_ + SQ_SIZE + SK_SIZE;

    int tid  = threadIdx.x;
    int wid  = tid >> 5;
    int lane = tid & 31;
    int gid  = lane >> 2;
    int tig  = lane & 3;

    int q0 = blockIdx.x * 128;
    int h  = blockIdx.y;
    int bz = blockIdx.z;
    int b  = bz >> 1, sp = bz & 1;
    size_t base = (size_t)b * NN;
    int qkcol = h * TWO_D + sp * 64;
    int vcol  = h * TWO_D;
    float* O = sp ? O2 : O1;

    // stage Q (scaled by SCALE), 128 rows x 64 dims
    {
        int c4 = tid & 15, r0 = tid >> 4;
#pragma unroll
        for (int p = 0; p < 8; p++) {
            int r = r0 + p * 16;
            float4 qv = *(const float4*)&Q[(base + q0 + r) * (2*CC) + qkcol + c4 * 4];
            uint32_t* d = &sQ[r * SQ_STR + c4 * 4];
            d[0] = f2tf32(qv.x * SCALE); d[1] = f2tf32(qv.y * SCALE);
            d[2] = f2tf32(qv.z * SCALE); d[3] = f2tf32(qv.w * SCALE);
        }
    }

    float o[16][4];
#pragma unroll
    for (int j = 0; j < 16; j++)
#pragma unroll
        for (int r = 0; r < 4; r++) o[j][r] = 0.f;
    float m0 = -1e30f, m1 = -1e30f, l0 = 0.f, l1 = 0.f;

    for (int t = 0; t < NN / 64; t++) {
        __syncthreads();
        // stage K tile (64x64) and V tile (64x128)
#pragma unroll
        for (int p = 0; p < 4; p++) {
            int e = tid + p * 256;
            int r = e >> 4, c4 = e & 15;
            float4 kv = *(const float4*)&K[(base + t*64 + r) * (2*CC) + qkcol + c4 * 4];
            uint32_t* d = &sK[r * SK_STR + c4 * 4];
            d[0] = f2tf32(kv.x); d[1] = f2tf32(kv.y);
            d[2] = f2tf32(kv.z); d[3] = f2tf32(kv.w);
        }
#pragma unroll
        for (int p = 0; p < 8; p++) {
            int e = tid + p * 256;
            int r = e >> 5, c4 = e & 31;
            float4 vv = *(const float4*)&Vv[(base + t*64 + r) * (2*CC) + vcol + c4 * 4];
            uint32_t* d = &sV[r * SV_STR + c4 * 4];
            d[0] = f2tf32(vv.x); d[1] = f2tf32(vv.y);
            d[2] = f2tf32(vv.z); d[3] = f2tf32(vv.w);
        }
        __syncthreads();

        // S = Q K^T (16 rows x 64 keys per warp)
        float s_[8][4];
#pragma unroll
        for (int j = 0; j < 8; j++)
#pragma unroll
            for (int r = 0; r < 4; r++) s_[j][r] = 0.f;
        int ar = wid * 16 + gid;
#pragma unroll
        for (int kc = 0; kc < 8; kc++) {
            uint32_t a[4];
            a[0] = sQ[ ar      * SQ_STR + kc*8 + tig];
            a[1] = sQ[(ar + 8) * SQ_STR + kc*8 + tig];
            a[2] = sQ[ ar      * SQ_STR + kc*8 + 4 + tig];
            a[3] = sQ[(ar + 8) * SQ_STR + kc*8 + 4 + tig];
#pragma unroll
            for (int j = 0; j < 8; j++) {
                uint32_t bfr[2];
                bfr[0] = sK[(j*8 + gid) * SK_STR + kc*8 + tig];
                bfr[1] = sK[(j*8 + gid) * SK_STR + kc*8 + 4 + tig];
                mma_tf32(s_[j], a, bfr);
            }
        }

        // online softmax (rows gid and gid+8 of this warp)
        float rm0 = -1e30f, rm1 = -1e30f;
#pragma unroll
        for (int j = 0; j < 8; j++) {
            rm0 = fmaxf(rm0, fmaxf(s_[j][0], s_[j][1]));
            rm1 = fmaxf(rm1, fmaxf(s_[j][2], s_[j][3]));
        }
        rm0 = fmaxf(rm0, __shfl_xor_sync(0xffffffffu, rm0, 1));
        rm0 = fmaxf(rm0, __shfl_xor_sync(0xffffffffu, rm0, 2));
        rm1 = fmaxf(rm1, __shfl_xor_sync(0xffffffffu, rm1, 1));
        rm1 = fmaxf(rm1, __shfl_xor_sync(0xffffffffu, rm1, 2));
        float nm0 = fmaxf(m0, rm0), nm1 = fmaxf(m1, rm1);
        float f0 = __expf(m0 - nm0), f1 = __expf(m1 - nm1);
        float rs0 = 0.f, rs1 = 0.f;
#pragma unroll
        for (int j = 0; j < 8; j++) {
            s_[j][0] = __expf(s_[j][0] - nm0);
            s_[j][1] = __expf(s_[j][1] - nm0);
            s_[j][2] = __expf(s_[j][2] - nm1);
            s_[j][3] = __expf(s_[j][3] - nm1);
            rs0 += s_[j][0] + s_[j][1];
            rs1 += s_[j][2] + s_[j][3];
        }
        rs0 += __shfl_xor_sync(0xffffffffu, rs0, 1);
        rs0 += __shfl_xor_sync(0xffffffffu, rs0, 2);
        rs1 += __shfl_xor_sync(0xffffffffu, rs1, 1);
        rs1 += __shfl_xor_sync(0xffffffffu, rs1, 2);
        l0 = l0 * f0 + rs0;
        l1 = l1 * f1 + rs1;
        m0 = nm0; m1 = nm1;
#pragma unroll
        for (int j = 0; j < 16; j++) {
            o[j][0] *= f0; o[j][1] *= f0;
            o[j][2] *= f1; o[j][3] *= f1;
        }

        // O += P @ V : re-lay C-fragment P into A-fragments via shuffles
        int srcA = (lane & ~3) | (tig >> 1);
        int srcB = srcA + 2;
        bool odd = (tig & 1);
#pragma unroll
        for (int kc = 0; kc < 8; kc++) {
            float c0 = s_[kc][0], c1 = s_[kc][1], c2 = s_[kc][2], c3 = s_[kc][3];
            float x0 = __shfl_sync(0xffffffffu, c0, srcA);
            float x1 = __shfl_sync(0xffffffffu, c1, srcA);
            float y0 = __shfl_sync(0xffffffffu, c0, srcB);
            float y1 = __shfl_sync(0xffffffffu, c1, srcB);
            float z0 = __shfl_sync(0xffffffffu, c2, srcA);
            float z1 = __shfl_sync(0xffffffffu, c3, srcA);
            float w0 = __shfl_sync(0xffffffffu, c2, srcB);
            float w1 = __shfl_sync(0xffffffffu, c3, srcB);
            uint32_t a[4];
            a[0] = __float_as_uint(odd ? x1 : x0);   // P[gid][kc*8+tig]
            a[1] = __float_as_uint(odd ? z1 : z0);   // P[gid+8][kc*8+tig]
            a[2] = __float_as_uint(odd ? y1 : y0);   // P[gid][kc*8+tig+4]
            a[3] = __float_as_uint(odd ? w1 : w0);   // P[gid+8][kc*8+tig+4]
#pragma unroll
            for (int j = 0; j < 16; j++) {
                uint32_t bfr[2];
                bfr[0] = sV[(kc*8 +     tig) * SV_STR + j*8 + gid];
                bfr[1] = sV[(kc*8 + 4 + tig) * SV_STR + j*8 + gid];
                mma_tf32(o[j], a, bfr);
            }
        }
    }

    // epilogue: normalize, store split output
    float inv0 = 1.f / l0, inv1 = 1.f / l1;
    int row0 = q0 + wid * 16 + gid, row1 = row0 + 8;
#pragma unroll
    for (int j = 0; j < 16; j++) {
        int col = vcol + j*8 + tig*2;
        *(float2*)&O[(base + row0) * (2*CC) + col] = make_float2(o[j][0]*inv0, o[j][1]*inv0);
        *(float2*)&O[(base + row1) * (2*CC) + col] = make_float2(o[j][2]*inv1, o[j][3]*inv1);
    }
}

// ================= combine: diff + per-head LN(128) + scale =================
__global__ __launch_bounds__(128) void combine_kernel(
    const float* __restrict__ O1, const float* __restrict__ O2,
    const float* __restrict__ lamp, const float* __restrict__ lnw,
    const float* __restrict__ lnb, float* __restrict__ out)
{
    int row = blockIdx.x, h = blockIdx.y, tid = threadIdx.x;
    size_t idx = (size_t)row * (2*CC) + h * TWO_D + tid;
    float lam = lamp[0];
    float v = O1[idx] - lam * O2[idx];
    float s = v, sq = v * v;
#pragma unroll
    for (int off = 16; off >= 1; off >>= 1) {
        s  += __shfl_xor_sync(0xffffffffu, s,  off);
        sq += __shfl_xor_sync(0xffffffffu, sq, off);
    }
    __shared__ float ws[4], wq[4];
    __shared__ float smu, srs;
    int wid = tid >> 5, lane = tid & 31;
    if (lane == 0) { ws[wid] = s; wq[wid] = sq; }
    __syncthreads();
    if (tid == 0) {
        float S = ws[0]+ws[1]+ws[2]+ws[3];
        float Q = wq[0]+wq[1]+wq[2]+wq[3];
        float mu = S * (1.0f/128.0f);
        float var = Q * (1.0f/128.0f) - mu * mu;
        smu = mu; srs = rsqrtf(var + EPS);
    }
    __syncthreads();
    float y = (v - smu) * srs * lnw[tid] + lnb[tid];
    out[idx] = y * OUT_SCALE;
}

// ================= launch =================
extern "C" void kernel_launch(void* const* d_in, const int* in_sizes, int n_in,
                              void* d_out, int out_size)
{
    const float* x    = (const float*)d_in[0];
    const float* n1w  = (const float*)d_in[1];
    const float* n1b  = (const float*)d_in[2];
    const float* wq   = (const float*)d_in[3];
    const float* wk   = (const float*)d_in[4];
    const float* wv   = (const float*)d_in[5];
    const float* lam  = (const float*)d_in[6];
    const float* alnw = (const float*)d_in[7];
    const float* alnb = (const float*)d_in[8];
    const float* pw   = (const float*)d_in[9];
    const float* pb   = (const float*)d_in[10];
    const float* n2w  = (const float*)d_in[11];
    const float* n2b  = (const float*)d_in[12];
    const float* f1w  = (const float*)d_in[13];
    const float* f1b  = (const float*)d_in[14];
    const float* f2w  = (const float*)d_in[15];
    const float* f2b  = (const float*)d_in[16];
    float* out = (float*)d_out;

    float *xn, *q, *k, *v, *o1, *o2, *att, *xmid, *xn2, *hb;
    cudaGetSymbolAddress((void**)&xn,   g_xn);
    cudaGetSymbolAddress((void**)&q,    g_q);
    cudaGetSymbolAddress((void**)&k,    g_k);
    cudaGetSymbolAddress((void**)&v,    g_v);
    cudaGetSymbolAddress((void**)&o1,   g_o1);
    cudaGetSymbolAddress((void**)&o2,   g_o2);
    cudaGetSymbolAddress((void**)&att,  g_att);
    cudaGetSymbolAddress((void**)&xmid, g_xmid);
    cudaGetSymbolAddress((void**)&xn2,  g_xn2);
    cudaGetSymbolAddress((void**)&hb,   g_h);

    cudaFuncSetAttribute(attn_mma_kernel,
                         cudaFuncAttributeMaxDynamicSharedMemorySize, ATT_SMEM);

    // 1. LN1
    ln_kernel<<<MROWS, 256>>>(x, n1w, n1b, xn);
    // 2. QKV GEMMs (4096 x 1536 x 768)
    tc_gemm<0><<<dim3(1536/128, MROWS/128), 256>>>(xn, wq, nullptr, nullptr, q, MROWS, 1536, 768);
    tc_gemm<0><<<dim3(1536/128, MROWS/128), 256>>>(xn, wk, nullptr, nullptr, k, MROWS, 1536, 768);
    tc_gemm<0><<<dim3(1536/128, MROWS/128), 256>>>(xn, wv, nullptr, nullptr, v, MROWS, 1536, 768);
    // 3. flash attention per split on tensor cores
    attn_mma_kernel<<<dim3(NN/128, HH, BB*2), 256, ATT_SMEM>>>(q, k, v, o1, o2);
    // 3b. combine: diff + head-LN + scale
    combine_kernel<<<dim3(MROWS, HH), 128>>>(o1, o2, lam, alnw, alnb, att);
    // 4. proj + bias + residual (4096 x 768 x 1536)
    tc_gemm<1><<<dim3(768/128, MROWS/128), 256>>>(att, pw, pb, x, xmid, MROWS, 768, 1536);
    // 5. LN2
    ln_kernel<<<MROWS, 256>>>(xmid, n2w, n2b, xn2);
    // 6. fc1 + bias + GELU (4096 x 3072 x 768)
    tc_gemm<2><<<dim3(3072/128, MROWS/128), 256>>>(xn2, f1w, f1b, nullptr, hb, MROWS, 3072, 768);
    // 7. fc2 + bias + residual (4096 x 768 x 3072)
    tc_gemm<1><<<dim3(768/128, MROWS/128), 256>>>(hb, f2w, f2b, xmid, out, MROWS, 768, 3072);
}

// round 6
// speedup vs baseline: 1.0744x; 1.0744x over previous
#include <cuda_runtime.h>
#include <math.h>
#include <stdint.h>

// ---------------- problem constants ----------------
#define BB 4
#define NN 1024
#define CC 768
#define HH 12
#define TWO_D 128
#define MROWS (BB*NN)    // 4096
#define SCALE 0.125f     // D^-0.5
#define EPS 1e-5f
#define OUT_SCALE 0.8f   // 1 - LAMBDA_INIT

// ---------------- scratch (device globals; no alloc allowed) ----------------
__device__ float g_xn  [MROWS*CC];
__device__ float g_q   [MROWS*2*CC];
__device__ float g_k   [MROWS*2*CC];
__device__ float g_v   [MROWS*2*CC];
__device__ float g_o1  [MROWS*2*CC];
__device__ float g_o2  [MROWS*2*CC];
__device__ float g_att [MROWS*2*CC];
__device__ float g_xmid[MROWS*CC];
__device__ float g_xn2 [MROWS*CC];
__device__ float g_h   [MROWS*4*CC];

// ================= helpers =================
__device__ __forceinline__ uint32_t f2tf32(float f) {
    uint32_t r;
    asm("cvt.rna.tf32.f32 %0, %1;" : "=r"(r) : "f"(f));
    return r;
}
__device__ __forceinline__ void mma_tf32(float* c, const uint32_t* a, const uint32_t* b) {
    asm volatile("mma.sync.aligned.m16n8k8.row.col.f32.tf32.tf32.f32 "
        "{%0,%1,%2,%3}, {%4,%5,%6,%7}, {%8,%9}, {%0,%1,%2,%3};"
        : "+f"(c[0]), "+f"(c[1]), "+f"(c[2]), "+f"(c[3])
        : "r"(a[0]), "r"(a[1]), "r"(a[2]), "r"(a[3]), "r"(b[0]), "r"(b[1]));
}

// ================= LayerNorm over 768 =================
__global__ __launch_bounds__(256) void ln_kernel(
    const float* __restrict__ x, const float* __restrict__ w,
    const float* __restrict__ b, float* __restrict__ out)
{
    int row = blockIdx.x;
    int tid = threadIdx.x;
    const float* xr = x + (size_t)row * CC;
    float v0 = xr[tid], v1 = xr[tid + 256], v2 = xr[tid + 512];
    float s  = v0 + v1 + v2;
    float sq = v0*v0 + v1*v1 + v2*v2;
#pragma unroll
    for (int off = 16; off >= 1; off >>= 1) {
        s  += __shfl_xor_sync(0xffffffffu, s,  off);
        sq += __shfl_xor_sync(0xffffffffu, sq, off);
    }
    __shared__ float rs_[8], rq_[8];
    __shared__ float smu, srs;
    int wid = tid >> 5, lane = tid & 31;
    if (lane == 0) { rs_[wid] = s; rq_[wid] = sq; }
    __syncthreads();
    if (tid == 0) {
        float S = 0.f, Q = 0.f;
#pragma unroll
        for (int i = 0; i < 8; i++) { S += rs_[i]; Q += rq_[i]; }
        float mu = S / (float)CC;
        float var = Q / (float)CC - mu * mu;
        smu = mu; srs = rsqrtf(var + EPS);
    }
    __syncthreads();
    float mu = smu, r = srs;
    float* orow = out + (size_t)row * CC;
    orow[tid]       = (v0 - mu) * r * w[tid]       + b[tid];
    orow[tid + 256] = (v1 - mu) * r * w[tid + 256] + b[tid + 256];
    orow[tid + 512] = (v2 - mu) * r * w[tid + 512] + b[tid + 512];
}

// ================= TF32 mma.sync GEMM: C = A(MxK) * B(NxK)^T =================
// 128x128 tile, 8 warps (2m x 4n), 64x32 warp tile, double-buffered smem.
// 2 CTAs/SM (launch_bounds regs<=128): staging latency hidden by co-resident CTA.
#define KC 32
#define SSTRIDE 36
#define STAGE_U32 (128 * SSTRIDE)

template<int EPI>
__global__ __launch_bounds__(256, 2) void tc_gemm(
    const float* __restrict__ A, const float* __restrict__ B,
    const float* __restrict__ bias, const float* __restrict__ res,
    float* __restrict__ C, int M, int N, int K)
{
    __shared__ uint32_t sA[2][STAGE_U32];
    __shared__ uint32_t sB[2][STAGE_U32];

    int tid  = threadIdx.x;
    int wid  = tid >> 5;
    int lane = tid & 31;
    int wm = wid >> 2;
    int wn = wid & 3;
    int gid = lane >> 2;
    int tig = lane & 3;

    int m0 = blockIdx.y * 128, n0 = blockIdx.x * 128;

    int trow = tid >> 3;
    int tseg = tid & 7;

    float acc[4][4][4];
#pragma unroll
    for (int i = 0; i < 4; i++)
#pragma unroll
        for (int j = 0; j < 4; j++)
#pragma unroll
            for (int r = 0; r < 4; r++) acc[i][j][r] = 0.f;

    // stage chunk 0
#pragma unroll
    for (int p = 0; p < 4; p++) {
        int r = trow + p * 32;
        float4 a4 = *(const float4*)(A + (size_t)(m0 + r) * K + tseg * 4);
        float4 b4 = *(const float4*)(B + (size_t)(n0 + r) * K + tseg * 4);
        uint32_t* da = &sA[0][r * SSTRIDE + tseg * 4];
        uint32_t* db = &sB[0][r * SSTRIDE + tseg * 4];
        da[0] = f2tf32(a4.x); da[1] = f2tf32(a4.y);
        da[2] = f2tf32(a4.z); da[3] = f2tf32(a4.w);
        db[0] = f2tf32(b4.x); db[1] = f2tf32(b4.y);
        db[2] = f2tf32(b4.z); db[3] = f2tf32(b4.w);
    }
    __syncthreads();

    int Cn = K / KC;
    for (int c = 0; c < Cn; c++) {
        int s = c & 1;
        const uint32_t* As = sA[s];
        const uint32_t* Bs = sB[s];
#pragma unroll
        for (int ks = 0; ks < 4; ks++) {
            int k0 = ks * 8;
            uint32_t afr[4][4], bfr[4][2];
#pragma unroll
            for (int i = 0; i < 4; i++) {
                int rb = wm * 64 + i * 16;
                afr[i][0] = As[(rb + gid    ) * SSTRIDE + k0 + tig];
                afr[i][1] = As[(rb + 8 + gid) * SSTRIDE + k0 + tig];
                afr[i][2] = As[(rb + gid    ) * SSTRIDE + k0 + 4 + tig];
                afr[i][3] = As[(rb + 8 + gid) * SSTRIDE + k0 + 4 + tig];
            }
#pragma unroll
            for (int j = 0; j < 4; j++) {
                int cb = wn * 32 + j * 8;
                bfr[j][0] = Bs[(cb + gid) * SSTRIDE + k0 + tig];
                bfr[j][1] = Bs[(cb + gid) * SSTRIDE + k0 + 4 + tig];
            }
#pragma unroll
            for (int i = 0; i < 4; i++)
#pragma unroll
                for (int j = 0; j < 4; j++)
                    mma_tf32(acc[i][j], afr[i], bfr[j]);
        }

        if (c + 1 < Cn) {
            int s1 = s ^ 1;
            int k0n = (c + 1) * KC;
#pragma unroll
            for (int p = 0; p < 4; p++) {
                int r = trow + p * 32;
                float4 a4 = *(const float4*)(A + (size_t)(m0 + r) * K + k0n + tseg * 4);
                float4 b4 = *(const float4*)(B + (size_t)(n0 + r) * K + k0n + tseg * 4);
                uint32_t* da = &sA[s1][r * SSTRIDE + tseg * 4];
                uint32_t* db = &sB[s1][r * SSTRIDE + tseg * 4];
                da[0] = f2tf32(a4.x); da[1] = f2tf32(a4.y);
                da[2] = f2tf32(a4.z); da[3] = f2tf32(a4.w);
                db[0] = f2tf32(b4.x); db[1] = f2tf32(b4.y);
                db[2] = f2tf32(b4.z); db[3] = f2tf32(b4.w);
            }
            __syncthreads();
        }
    }

#pragma unroll
    for (int i = 0; i < 4; i++) {
#pragma unroll
        for (int j = 0; j < 4; j++) {
            int col = n0 + wn * 32 + j * 8 + tig * 2;
#pragma unroll
            for (int half = 0; half < 2; half++) {
                int row = m0 + wm * 64 + i * 16 + gid + half * 8;
                float vx = acc[i][j][half * 2 + 0];
                float vy = acc[i][j][half * 2 + 1];
                if (EPI == 1) {
                    const float* rrow = res + (size_t)row * N + col;
                    vx += bias[col]     + rrow[0];
                    vy += bias[col + 1] + rrow[1];
                } else if (EPI == 2) {
                    vx += bias[col];
                    vy += bias[col + 1];
                    vx = 0.5f * vx * (1.0f + erff(vx * 0.70710678118654752f));
                    vy = 0.5f * vy * (1.0f + erff(vy * 0.70710678118654752f));
                }
                float2 o = make_float2(vx, vy);
                *(float2*)(C + (size_t)row * N + col) = o;
            }
        }
    }
}

// ================= Flash attention (one split per block) on tf32 mma =================
// grid (8, 12, 8): x=q-tile(128 rows), y=head, z=b*2+split. 8 warps x 16 rows.
// 2 CTAs/SM target (smem 87KB <= 113KB, regs <= 128).
#define SQ_STR 68
#define SK_STR 68
#define SV_STR 136
#define SQ_SIZE (128*SQ_STR)
#define SK_SIZE (64*SK_STR)
#define SV_SIZE (64*SV_STR)
#define ATT_SMEM ((SQ_SIZE+SK_SIZE+SV_SIZE)*4)

__global__ __launch_bounds__(256, 2) void attn_mma_kernel(
    const float* __restrict__ Q, const float* __restrict__ K,
    const float* __restrict__ Vv, float* __restrict__ O1, float* __restrict__ O2)
{
    extern __shared__ uint32_t asm_[];
    uint32_t* sQ = asm_;
    uint32_t* sK = asm_ + SQ_SIZE;
    uint32_t* sV = asm_ + SQ_SIZE + SK_SIZE;

    int tid  = threadIdx.x;
    int wid  = tid >> 5;
    int lane = tid & 31;
    int gid  = lane >> 2;
    int tig  = lane & 3;

    int q0 = blockIdx.x * 128;
    int h  = blockIdx.y;
    int bz = blockIdx.z;
    int b  = bz >> 1, sp = bz & 1;
    size_t base = (size_t)b * NN;
    int qkcol = h * TWO_D + sp * 64;
    int vcol  = h * TWO_D;
    float* O = sp ? O2 : O1;

    // stage Q (scaled by SCALE), 128 rows x 64 dims
    {
        int c4 = tid & 15, r0 = tid >> 4;
#pragma unroll
        for (int p = 0; p < 8; p++) {
            int r = r0 + p * 16;
            float4 qv = *(const float4*)&Q[(base + q0 + r) * (2*CC) + qkcol + c4 * 4];
            uint32_t* d = &sQ[r * SQ_STR + c4 * 4];
            d[0] = f2tf32(qv.x * SCALE); d[1] = f2tf32(qv.y * SCALE);
            d[2] = f2tf32(qv.z * SCALE); d[3] = f2tf32(qv.w * SCALE);
        }
    }

    float o[16][4];
#pragma unroll
    for (int j = 0; j < 16; j++)
#pragma unroll
        for (int r = 0; r < 4; r++) o[j][r] = 0.f;
    float m0 = -1e30f, m1 = -1e30f, l0 = 0.f, l1 = 0.f;

    for (int t = 0; t < NN / 64; t++) {
        __syncthreads();
        // stage K tile (64x64) and V tile (64x128)
#pragma unroll
        for (int p = 0; p < 4; p++) {
            int e = tid + p * 256;
            int r = e >> 4, c4 = e & 15;
            float4 kv = *(const float4*)&K[(base + t*64 + r) * (2*CC) + qkcol + c4 * 4];
            uint32_t* d = &sK[r * SK_STR + c4 * 4];
            d[0] = f2tf32(kv.x); d[1] = f2tf32(kv.y);
            d[2] = f2tf32(kv.z); d[3] = f2tf32(kv.w);
        }
#pragma unroll
        for (int p = 0; p < 8; p++) {
            int e = tid + p * 256;
            int r = e >> 5, c4 = e & 31;
            float4 vv = *(const float4*)&Vv[(base + t*64 + r) * (2*CC) + vcol + c4 * 4];
            uint32_t* d = &sV[r * SV_STR + c4 * 4];
            d[0] = f2tf32(vv.x); d[1] = f2tf32(vv.y);
            d[2] = f2tf32(vv.z); d[3] = f2tf32(vv.w);
        }
        __syncthreads();

        // S = Q K^T (16 rows x 64 keys per warp)
        float s_[8][4];
#pragma unroll
        for (int j = 0; j < 8; j++)
#pragma unroll
            for (int r = 0; r < 4; r++) s_[j][r] = 0.f;
        int ar = wid * 16 + gid;
#pragma unroll
        for (int kc = 0; kc < 8; kc++) {
            uint32_t a[4];
            a[0] = sQ[ ar      * SQ_STR + kc*8 + tig];
            a[1] = sQ[(ar + 8) * SQ_STR + kc*8 + tig];
            a[2] = sQ[ ar      * SQ_STR + kc*8 + 4 + tig];
            a[3] = sQ[(ar + 8) * SQ_STR + kc*8 + 4 + tig];
#pragma unroll
            for (int j = 0; j < 8; j++) {
                uint32_t bfr[2];
                bfr[0] = sK[(j*8 + gid) * SK_STR + kc*8 + tig];
                bfr[1] = sK[(j*8 + gid) * SK_STR + kc*8 + 4 + tig];
                mma_tf32(s_[j], a, bfr);
            }
        }

        // online softmax (rows gid and gid+8 of this warp)
        float rm0 = -1e30f, rm1 = -1e30f;
#pragma unroll
        for (int j = 0; j < 8; j++) {
            rm0 = fmaxf(rm0, fmaxf(s_[j][0], s_[j][1]));
            rm1 = fmaxf(rm1, fmaxf(s_[j][2], s_[j][3]));
        }
        rm0 = fmaxf(rm0, __shfl_xor_sync(0xffffffffu, rm0, 1));
        rm0 = fmaxf(rm0, __shfl_xor_sync(0xffffffffu, rm0, 2));
        rm1 = fmaxf(rm1, __shfl_xor_sync(0xffffffffu, rm1, 1));
        rm1 = fmaxf(rm1, __shfl_xor_sync(0xffffffffu, rm1, 2));
        float nm0 = fmaxf(m0, rm0), nm1 = fmaxf(m1, rm1);
        float f0 = __expf(m0 - nm0), f1 = __expf(m1 - nm1);
        float rs0 = 0.f, rs1 = 0.f;
#pragma unroll
        for (int j = 0; j < 8; j++) {
            s_[j][0] = __expf(s_[j][0] - nm0);
            s_[j][1] = __expf(s_[j][1] - nm0);
            s_[j][2] = __expf(s_[j][2] - nm1);
            s_[j][3] = __expf(s_[j][3] - nm1);
            rs0 += s_[j][0] + s_[j][1];
            rs1 += s_[j][2] + s_[j][3];
        }
        rs0 += __shfl_xor_sync(0xffffffffu, rs0, 1);
        rs0 += __shfl_xor_sync(0xffffffffu, rs0, 2);
        rs1 += __shfl_xor_sync(0xffffffffu, rs1, 1);
        rs1 += __shfl_xor_sync(0xffffffffu, rs1, 2);
        l0 = l0 * f0 + rs0;
        l1 = l1 * f1 + rs1;
        m0 = nm0; m1 = nm1;
#pragma unroll
        for (int j = 0; j < 16; j++) {
            o[j][0] *= f0; o[j][1] *= f0;
            o[j][2] *= f1; o[j][3] *= f1;
        }

        // O += P @ V : re-lay C-fragment P into A-fragments via shuffles
        int srcA = (lane & ~3) | (tig >> 1);
        int srcB = srcA + 2;
        bool odd = (tig & 1);
#pragma unroll
        for (int kc = 0; kc < 8; kc++) {
            float c0 = s_[kc][0], c1 = s_[kc][1], c2 = s_[kc][2], c3 = s_[kc][3];
            float x0 = __shfl_sync(0xffffffffu, c0, srcA);
            float x1 = __shfl_sync(0xffffffffu, c1, srcA);
            float y0 = __shfl_sync(0xffffffffu, c0, srcB);
            float y1 = __shfl_sync(0xffffffffu, c1, srcB);
            float z0 = __shfl_sync(0xffffffffu, c2, srcA);
            float z1 = __shfl_sync(0xffffffffu, c3, srcA);
            float w0 = __shfl_sync(0xffffffffu, c2, srcB);
            float w1 = __shfl_sync(0xffffffffu, c3, srcB);
            uint32_t a[4];
            a[0] = __float_as_uint(odd ? x1 : x0);
            a[1] = __float_as_uint(odd ? z1 : z0);
            a[2] = __float_as_uint(odd ? y1 : y0);
            a[3] = __float_as_uint(odd ? w1 : w0);
#pragma unroll
            for (int j = 0; j < 16; j++) {
                uint32_t bfr[2];
                bfr[0] = sV[(kc*8 +     tig) * SV_STR + j*8 + gid];
                bfr[1] = sV[(kc*8 + 4 + tig) * SV_STR + j*8 + gid];
                mma_tf32(o[j], a, bfr);
            }
        }
    }

    // epilogue: normalize, store split output
    float inv0 = 1.f / l0, inv1 = 1.f / l1;
    int row0 = q0 + wid * 16 + gid, row1 = row0 + 8;
#pragma unroll
    for (int j = 0; j < 16; j++) {
        int col = vcol + j*8 + tig*2;
        *(float2*)&O[(base + row0) * (2*CC) + col] = make_float2(o[j][0]*inv0, o[j][1]*inv0);
        *(float2*)&O[(base + row1) * (2*CC) + col] = make_float2(o[j][2]*inv1, o[j][3]*inv1);
    }
}

// ================= combine: diff + per-head LN(128) + scale =================
__global__ __launch_bounds__(128) void combine_kernel(
    const float* __restrict__ O1, const float* __restrict__ O2,
    const float* __restrict__ lamp, const float* __restrict__ lnw,
    const float* __restrict__ lnb, float* __restrict__ out)
{
    int row = blockIdx.x, h = blockIdx.y, tid = threadIdx.x;
    size_t idx = (size_t)row * (2*CC) + h * TWO_D + tid;
    float lam = lamp[0];
    float v = O1[idx] - lam * O2[idx];
    float s = v, sq = v * v;
#pragma unroll
    for (int off = 16; off >= 1; off >>= 1) {
        s  += __shfl_xor_sync(0xffffffffu, s,  off);
        sq += __shfl_xor_sync(0xffffffffu, sq, off);
    }
    __shared__ float ws[4], wq[4];
    __shared__ float smu, srs;
    int wid = tid >> 5, lane = tid & 31;
    if (lane == 0) { ws[wid] = s; wq[wid] = sq; }
    __syncthreads();
    if (tid == 0) {
        float S = ws[0]+ws[1]+ws[2]+ws[3];
        float Q = wq[0]+wq[1]+wq[2]+wq[3];
        float mu = S * (1.0f/128.0f);
        float var = Q * (1.0f/128.0f) - mu * mu;
        smu = mu; srs = rsqrtf(var + EPS);
    }
    __syncthreads();
    float y = (v - smu) * srs * lnw[tid] + lnb[tid];
    out[idx] = y * OUT_SCALE;
}

// ================= launch =================
extern "C" void kernel_launch(void* const* d_in, const int* in_sizes, int n_in,
                              void* d_out, int out_size)
{
    const float* x    = (const float*)d_in[0];
    const float* n1w  = (const float*)d_in[1];
    const float* n1b  = (const float*)d_in[2];
    const float* wq   = (const float*)d_in[3];
    const float* wk   = (const float*)d_in[4];
    const float* wv   = (const float*)d_in[5];
    const float* lam  = (const float*)d_in[6];
    const float* alnw = (const float*)d_in[7];
    const float* alnb = (const float*)d_in[8];
    const float* pw   = (const float*)d_in[9];
    const float* pb   = (const float*)d_in[10];
    const float* n2w  = (const float*)d_in[11];
    const float* n2b  = (const float*)d_in[12];
    const float* f1w  = (const float*)d_in[13];
    const float* f1b  = (const float*)d_in[14];
    const float* f2w  = (const float*)d_in[15];
    const float* f2b  = (const float*)d_in[16];
    float* out = (float*)d_out;

    float *xn, *q, *k, *v, *o1, *o2, *att, *xmid, *xn2, *hb;
    cudaGetSymbolAddress((void**)&xn,   g_xn);
    cudaGetSymbolAddress((void**)&q,    g_q);
    cudaGetSymbolAddress((void**)&k,    g_k);
    cudaGetSymbolAddress((void**)&v,    g_v);
    cudaGetSymbolAddress((void**)&o1,   g_o1);
    cudaGetSymbolAddress((void**)&o2,   g_o2);
    cudaGetSymbolAddress((void**)&att,  g_att);
    cudaGetSymbolAddress((void**)&xmid, g_xmid);
    cudaGetSymbolAddress((void**)&xn2,  g_xn2);
    cudaGetSymbolAddress((void**)&hb,   g_h);

    cudaFuncSetAttribute(attn_mma_kernel,
                         cudaFuncAttributeMaxDynamicSharedMemorySize, ATT_SMEM);

    // 1. LN1
    ln_kernel<<<MROWS, 256>>>(x, n1w, n1b, xn);
    // 2. QKV GEMMs (4096 x 1536 x 768)
    tc_gemm<0><<<dim3(1536/128, MROWS/128), 256>>>(xn, wq, nullptr, nullptr, q, MROWS, 1536, 768);
    tc_gemm<0><<<dim3(1536/128, MROWS/128), 256>>>(xn, wk, nullptr, nullptr, k, MROWS, 1536, 768);
    tc_gemm<0><<<dim3(1536/128, MROWS/128), 256>>>(xn, wv, nullptr, nullptr, v, MROWS, 1536, 768);
    // 3. flash attention per split on tensor cores
    attn_mma_kernel<<<dim3(NN/128, HH, BB*2), 256, ATT_SMEM>>>(q, k, v, o1, o2);
    // 3b. combine: diff + head-LN + scale
    combine_kernel<<<dim3(MROWS, HH), 128>>>(o1, o2, lam, alnw, alnb, att);
    // 4. proj + bias + residual (4096 x 768 x 1536)
    tc_gemm<1><<<dim3(768/128, MROWS/128), 256>>>(att, pw, pb, x, xmid, MROWS, 768, 1536);
    // 5. LN2
    ln_kernel<<<MROWS, 256>>>(xmid, n2w, n2b, xn2);
    // 6. fc1 + bias + GELU (4096 x 3072 x 768)
    tc_gemm<2><<<dim3(3072/128, MROWS/128), 256>>>(xn2, f1w, f1b, nullptr, hb, MROWS, 3072, 768);
    // 7. fc2 + bias + residual (4096 x 768 x 3072)
    tc_gemm<1><<<dim3(768/128, MROWS/128), 256>>>(hb, f2w, f2b, xmid, out, MROWS, 768, 3072);
}